// round 16
// baseline (speedup 1.0000x reference)
#include <cuda_runtime.h>
#include <cuda_bf16.h>

// ---------------------------------------------------------------------------
// Nodes_Embedding via tensor cores (mma.sync.m16n8k16.bf16):
//   out[a,:] = ELU(ELU(ELU(x W1^T + b1) W2^T + b2) W3^T + b3)
//              + (float)part[a] + charge[part[a]]
// N = 4M, D = 16.  atom_part arrives int32 (harness dtype contract).
//
// R16: streaming cache hints on the zero-reuse streams -- __ldcs on atv/part
// loads, __stcs on out stores (evict-first; stop L2 churn + write-allocate
// pollution on 528 MB of stream traffic). charge/weights keep default policy
// (cross-block reuse). Everything else identical to R15: smem (i+charge[i])
// table, bf16x2 packed ELU, layer-0 k-permutation (float4 A loads), layer-2
// n-permutation (STG.128), depth-1 software pipeline, launch_bounds(128,8).
// ---------------------------------------------------------------------------

static constexpr int BLOCK = 128;                  // 4 warps
static constexpr int WARPS = BLOCK / 32;
static constexpr int TPW   = 8;                    // 16-atom tiles per warp
static constexpr int ABLK  = WARPS * TPW * 16;     // 512 atoms per block
static constexpr int TABLE = 2048;                 // smem charge-table capacity

__device__ __forceinline__ unsigned pack_bf16(float lo, float hi) {
    __nv_bfloat162 h = __floats2bfloat162_rn(lo, hi);  // .x = lo half
    return *reinterpret_cast<unsigned*>(&h);
}

// scalar elu (final layer, fp32)
__device__ __forceinline__ float elu1(float v) {
    float em1 = __expf(v) - 1.0f;
    return v > 0.0f ? v : em1;
}

// packed elu on a bf16x2 pair: elu(x) = max(x,0) + min(exp(x)-1, 0)
__device__ __forceinline__ unsigned elu_bf16x2(unsigned x) {
    const unsigned LOG2E2 = 0x3FB93FB9u;  // bf16(log2 e) x2
    const unsigned NEG1X2 = 0xBF80BF80u;  // bf16(-1) x2
    const unsigned ZERO2  = 0x00000000u;
    unsigned y, e, em1, mx, mn, r;
    asm("mul.rn.bf16x2 %0, %1, %2;"      : "=r"(y)   : "r"(x),   "r"(LOG2E2));
    asm("ex2.approx.ftz.bf16x2 %0, %1;"  : "=r"(e)   : "r"(y));
    asm("add.rn.bf16x2 %0, %1, %2;"      : "=r"(em1) : "r"(e),   "r"(NEG1X2));
    asm("max.bf16x2 %0, %1, %2;"         : "=r"(mx)  : "r"(x),   "r"(ZERO2));
    asm("min.bf16x2 %0, %1, %2;"         : "=r"(mn)  : "r"(em1), "r"(ZERO2));
    asm("add.rn.bf16x2 %0, %1, %2;"      : "=r"(r)   : "r"(mx),  "r"(mn));
    return r;
}

__device__ __forceinline__ void mma_16816(float& c0, float& c1, float& c2, float& c3,
                                          unsigned a0, unsigned a1, unsigned a2, unsigned a3,
                                          unsigned b0, unsigned b1) {
    asm("mma.sync.aligned.m16n8k16.row.col.f32.bf16.bf16.f32 "
        "{%0,%1,%2,%3}, {%4,%5,%6,%7}, {%8,%9}, {%0,%1,%2,%3};"
        : "+f"(c0), "+f"(c1), "+f"(c2), "+f"(c3)
        : "r"(a0), "r"(a1), "r"(a2), "r"(a3), "r"(b0), "r"(b1));
}

__global__ void __launch_bounds__(BLOCK, 8)
nodes_embedding_kernel(const float* __restrict__ atv,      // [N,16]
                       const float* __restrict__ charge,   // [nParts]
                       const float* __restrict__ W1, const float* __restrict__ b1,
                       const float* __restrict__ W2, const float* __restrict__ b2,
                       const float* __restrict__ W3, const float* __restrict__ b3,
                       const int* __restrict__ part,       // [N] int32
                       float* __restrict__ out,            // [N,16]
                       int nAtoms, int nParts) {
    const int lane = threadIdx.x & 31;
    const int wid  = threadIdx.x >> 5;
    const int g = lane >> 2;       // groupID
    const int t = lane & 3;        // threadID_in_group

    // ---- shared: precomputed  s_val[i] = (float)i + charge[i] ---------------
    __shared__ float s_val[TABLE];
    const int tn = nParts < TABLE ? nParts : TABLE;
    for (int i = threadIdx.x; i < tn; i += BLOCK)
        s_val[i] = (float)i + charge[i];
    __syncthreads();

    // ---- thread-resident weights (bf16 pairs) and biases --------------------
    unsigned bw[3][2][2];   // [layer][n-half][k-reg]
    float    bias[3][4];
    {
        // layer 0: k-permuted (k slots = {4t..4t+3}) -> float4 A loads
        bw[0][0][0] = pack_bf16(W1[g * 16 + 4 * t],           W1[g * 16 + 4 * t + 1]);
        bw[0][0][1] = pack_bf16(W1[g * 16 + 4 * t + 2],       W1[g * 16 + 4 * t + 3]);
        bw[0][1][0] = pack_bf16(W1[(g + 8) * 16 + 4 * t],     W1[(g + 8) * 16 + 4 * t + 1]);
        bw[0][1][1] = pack_bf16(W1[(g + 8) * 16 + 4 * t + 2], W1[(g + 8) * 16 + 4 * t + 3]);
        // layer 1: standard (C layout == A layout chaining)
        bw[1][0][0] = pack_bf16(W2[g * 16 + 2 * t],           W2[g * 16 + 2 * t + 1]);
        bw[1][0][1] = pack_bf16(W2[g * 16 + 2 * t + 8],       W2[g * 16 + 2 * t + 9]);
        bw[1][1][0] = pack_bf16(W2[(g + 8) * 16 + 2 * t],     W2[(g + 8) * 16 + 2 * t + 1]);
        bw[1][1][1] = pack_bf16(W2[(g + 8) * 16 + 2 * t + 8], W2[(g + 8) * 16 + 2 * t + 9]);
        // layer 2: n-permuted -> contiguous per-thread outputs (STG.128)
        const int pg = 4 * (g >> 1) + (g & 1);
        bw[2][0][0] = pack_bf16(W3[pg * 16 + 2 * t],           W3[pg * 16 + 2 * t + 1]);
        bw[2][0][1] = pack_bf16(W3[pg * 16 + 2 * t + 8],       W3[pg * 16 + 2 * t + 9]);
        bw[2][1][0] = pack_bf16(W3[(pg + 2) * 16 + 2 * t],     W3[(pg + 2) * 16 + 2 * t + 1]);
        bw[2][1][1] = pack_bf16(W3[(pg + 2) * 16 + 2 * t + 8], W3[(pg + 2) * 16 + 2 * t + 9]);

        bias[0][0] = b1[2 * t];     bias[0][1] = b1[2 * t + 1];
        bias[0][2] = b1[8 + 2 * t]; bias[0][3] = b1[8 + 2 * t + 1];
        bias[1][0] = b2[2 * t];     bias[1][1] = b2[2 * t + 1];
        bias[1][2] = b2[8 + 2 * t]; bias[1][3] = b2[8 + 2 * t + 1];
        bias[2][0] = b3[4 * t];     bias[2][1] = b3[4 * t + 1];
        bias[2][2] = b3[4 * t + 2]; bias[2][3] = b3[4 * t + 3];
    }

    const int tileBase0 = blockIdx.x * ABLK + wid * (TPW * 16);

    // ---- prefetch tile 0: A fragments + part indices (streaming loads) ------
    float4 pfA = make_float4(0.f, 0.f, 0.f, 0.f);
    float4 pfB = pfA;
    int    pfP0 = 0, pfP1 = 0;
    {
        const int r0 = tileBase0 + g, r1 = r0 + 8;
        if (r0 < nAtoms) {
            pfA  = __ldcs(reinterpret_cast<const float4*>(atv + (size_t)r0 * 16 + 4 * t));
            pfP0 = __ldcs(part + r0);
        }
        if (r1 < nAtoms) {
            pfB  = __ldcs(reinterpret_cast<const float4*>(atv + (size_t)r1 * 16 + 4 * t));
            pfP1 = __ldcs(part + r1);
        }
    }

#pragma unroll 1
    for (int tt = 0; tt < TPW; ++tt) {
        const int TB = tileBase0 + tt * 16;
        const int r0 = TB + g;
        const int r1 = TB + g + 8;
        const bool v0 = r0 < nAtoms;
        const bool v1 = r1 < nAtoms;

        // consume prefetch
        const float4 cA = pfA;
        const float4 cB = pfB;
        const int    p0 = pfP0;
        const int    p1 = pfP1;

        // issue next tile's loads early (overlap with this tile's compute)
        if (tt + 1 < TPW) {
            const int n0 = r0 + 16, n1 = r1 + 16;
            pfA = make_float4(0.f, 0.f, 0.f, 0.f);
            pfB = pfA;
            pfP0 = 0; pfP1 = 0;
            if (n0 < nAtoms) {
                pfA  = __ldcs(reinterpret_cast<const float4*>(atv + (size_t)n0 * 16 + 4 * t));
                pfP0 = __ldcs(part + n0);
            }
            if (n1 < nAtoms) {
                pfB  = __ldcs(reinterpret_cast<const float4*>(atv + (size_t)n1 * 16 + 4 * t));
                pfP1 = __ldcs(part + n1);
            }
        }

        // ---- A fragment (layer-0 permuted k) --------------------------------
        unsigned a0 = pack_bf16(cA.x, cA.y);
        unsigned a2 = pack_bf16(cA.z, cA.w);
        unsigned a1 = pack_bf16(cB.x, cB.y);
        unsigned a3 = pack_bf16(cB.z, cB.w);

        // ---- 3 chained layers; packed bf16x2 ELU between layers --------------
        float cl[4], ch[4];
#pragma unroll
        for (int l = 0; l < 3; ++l) {
            cl[0] = bias[l][0]; cl[1] = bias[l][1]; cl[2] = bias[l][0]; cl[3] = bias[l][1];
            ch[0] = bias[l][2]; ch[1] = bias[l][3]; ch[2] = bias[l][2]; ch[3] = bias[l][3];
            mma_16816(cl[0], cl[1], cl[2], cl[3], a0, a1, a2, a3, bw[l][0][0], bw[l][0][1]);
            mma_16816(ch[0], ch[1], ch[2], ch[3], a0, a1, a2, a3, bw[l][1][0], bw[l][1][1]);
            if (l < 2) {
                a0 = elu_bf16x2(pack_bf16(cl[0], cl[1]));
                a1 = elu_bf16x2(pack_bf16(cl[2], cl[3]));
                a2 = elu_bf16x2(pack_bf16(ch[0], ch[1]));
                a3 = elu_bf16x2(pack_bf16(ch[2], ch[3]));
            }
        }

        // ---- epilogue add from shared table ----------------------------------
        int pc0 = p0 < 0 ? 0 : (p0 >= tn ? tn - 1 : p0);
        int pc1 = p1 < 0 ? 0 : (p1 >= tn ? tn - 1 : p1);
        const float av0 = s_val[pc0];
        const float av1 = s_val[pc1];

        // ---- final ELU (fp32) + add + contiguous streaming STG.128 -----------
        if (v0) {
            float4 s;
            s.x = elu1(cl[0]) + av0;
            s.y = elu1(cl[1]) + av0;
            s.z = elu1(ch[0]) + av0;
            s.w = elu1(ch[1]) + av0;
            __stcs(reinterpret_cast<float4*>(out + (size_t)r0 * 16 + 4 * t), s);
        }
        if (v1) {
            float4 s;
            s.x = elu1(cl[2]) + av1;
            s.y = elu1(cl[3]) + av1;
            s.z = elu1(ch[2]) + av1;
            s.w = elu1(ch[3]) + av1;
            __stcs(reinterpret_cast<float4*>(out + (size_t)r1 * 16 + 4 * t), s);
        }
    }
}

extern "C" void kernel_launch(void* const* d_in, const int* in_sizes, int n_in,
                              void* d_out, int out_size) {
    // ---- bind inputs by element count (order-independent) ------------------
    const float* Ws[3] = {nullptr, nullptr, nullptr};
    const float* bs[3] = {nullptr, nullptr, nullptr};
    const float* charge = nullptr;
    int wi = 0, bi = 0, chargeN = 1024;

    int bigIdx[2] = {-1, -1};
    long long bigSz[2] = {-1, -1};

    for (int i = 0; i < n_in; ++i) {
        long long s = in_sizes[i];
        if (s == 256 && wi < 3) {
            Ws[wi++] = (const float*)d_in[i];
        } else if (s == 16 && bi < 3) {
            bs[bi++] = (const float*)d_in[i];
        } else if (s >= 512 && s <= 65536 && s != 256) {
            charge = (const float*)d_in[i];
            chargeN = (int)s;
        } else if (s > 65536) {
            if (s > bigSz[0]) {
                bigSz[1] = bigSz[0]; bigIdx[1] = bigIdx[0];
                bigSz[0] = s;        bigIdx[0] = i;
            } else if (s > bigSz[1]) {
                bigSz[1] = s;        bigIdx[1] = i;
            }
        }
    }

    const float* atv  = (const float*)d_in[bigIdx[0]];  // 16*N elems
    const int*   part = (const int*)d_in[bigIdx[1]];    // N elems, int32
    float*       out  = (float*)d_out;

    int nAtoms = (int)bigSz[1];
    if ((long long)nAtoms * 16 != bigSz[0]) {
        nAtoms = (int)(bigSz[0] / 16);
    }

    int grid = (nAtoms + ABLK - 1) / ABLK;
    nodes_embedding_kernel<<<grid, BLOCK>>>(atv, charge, Ws[0], bs[0], Ws[1], bs[1],
                                            Ws[2], bs[2], part, out, nAtoms, chargeN);
}

// round 17
// speedup vs baseline: 1.1997x; 1.1997x over previous
#include <cuda_runtime.h>
#include <cuda_bf16.h>

// ---------------------------------------------------------------------------
// Nodes_Embedding via tensor cores (mma.sync.m16n8k16.bf16):
//   out[a,:] = ELU(ELU(ELU(x W1^T + b1) W2^T + b2) W3^T + b3)
//              + (float)part[a] + charge[part[a]]
// N = 4M, D = 16.  atom_part arrives int32 (harness dtype contract).
//
// R17: REVERT R16's streaming hints (regressed 92->115 us: .cs path produced
// a worse L1/instruction stream, dram fell 67->52%). Back to default-policy
// loads/stores (R15 config) + TPW 8->16 to halve per-block setup and
// pipeline fill/drain share. Keeps: smem (i+charge[i]) table, bf16x2 packed
// ELU, layer-0 k-permutation (float4 A loads), layer-2 n-permutation
// (STG.128), depth-1 software pipeline, __launch_bounds__(128,8).
// ---------------------------------------------------------------------------

static constexpr int BLOCK = 128;                  // 4 warps
static constexpr int WARPS = BLOCK / 32;
static constexpr int TPW   = 16;                   // 16-atom tiles per warp
static constexpr int ABLK  = WARPS * TPW * 16;     // 1024 atoms per block
static constexpr int TABLE = 2048;                 // smem charge-table capacity

__device__ __forceinline__ unsigned pack_bf16(float lo, float hi) {
    __nv_bfloat162 h = __floats2bfloat162_rn(lo, hi);  // .x = lo half
    return *reinterpret_cast<unsigned*>(&h);
}

// scalar elu (final layer, fp32)
__device__ __forceinline__ float elu1(float v) {
    float em1 = __expf(v) - 1.0f;
    return v > 0.0f ? v : em1;
}

// packed elu on a bf16x2 pair: elu(x) = max(x,0) + min(exp(x)-1, 0)
__device__ __forceinline__ unsigned elu_bf16x2(unsigned x) {
    const unsigned LOG2E2 = 0x3FB93FB9u;  // bf16(log2 e) x2
    const unsigned NEG1X2 = 0xBF80BF80u;  // bf16(-1) x2
    const unsigned ZERO2  = 0x00000000u;
    unsigned y, e, em1, mx, mn, r;
    asm("mul.rn.bf16x2 %0, %1, %2;"      : "=r"(y)   : "r"(x),   "r"(LOG2E2));
    asm("ex2.approx.ftz.bf16x2 %0, %1;"  : "=r"(e)   : "r"(y));
    asm("add.rn.bf16x2 %0, %1, %2;"      : "=r"(em1) : "r"(e),   "r"(NEG1X2));
    asm("max.bf16x2 %0, %1, %2;"         : "=r"(mx)  : "r"(x),   "r"(ZERO2));
    asm("min.bf16x2 %0, %1, %2;"         : "=r"(mn)  : "r"(em1), "r"(ZERO2));
    asm("add.rn.bf16x2 %0, %1, %2;"      : "=r"(r)   : "r"(mx),  "r"(mn));
    return r;
}

__device__ __forceinline__ void mma_16816(float& c0, float& c1, float& c2, float& c3,
                                          unsigned a0, unsigned a1, unsigned a2, unsigned a3,
                                          unsigned b0, unsigned b1) {
    asm("mma.sync.aligned.m16n8k16.row.col.f32.bf16.bf16.f32 "
        "{%0,%1,%2,%3}, {%4,%5,%6,%7}, {%8,%9}, {%0,%1,%2,%3};"
        : "+f"(c0), "+f"(c1), "+f"(c2), "+f"(c3)
        : "r"(a0), "r"(a1), "r"(a2), "r"(a3), "r"(b0), "r"(b1));
}

__global__ void __launch_bounds__(BLOCK, 8)
nodes_embedding_kernel(const float* __restrict__ atv,      // [N,16]
                       const float* __restrict__ charge,   // [nParts]
                       const float* __restrict__ W1, const float* __restrict__ b1,
                       const float* __restrict__ W2, const float* __restrict__ b2,
                       const float* __restrict__ W3, const float* __restrict__ b3,
                       const int* __restrict__ part,       // [N] int32
                       float* __restrict__ out,            // [N,16]
                       int nAtoms, int nParts) {
    const int lane = threadIdx.x & 31;
    const int wid  = threadIdx.x >> 5;
    const int g = lane >> 2;       // groupID
    const int t = lane & 3;        // threadID_in_group

    // ---- shared: precomputed  s_val[i] = (float)i + charge[i] ---------------
    __shared__ float s_val[TABLE];
    const int tn = nParts < TABLE ? nParts : TABLE;
    for (int i = threadIdx.x; i < tn; i += BLOCK)
        s_val[i] = (float)i + charge[i];
    __syncthreads();

    // ---- thread-resident weights (bf16 pairs) and biases --------------------
    unsigned bw[3][2][2];   // [layer][n-half][k-reg]
    float    bias[3][4];
    {
        // layer 0: k-permuted (k slots = {4t..4t+3}) -> float4 A loads
        bw[0][0][0] = pack_bf16(W1[g * 16 + 4 * t],           W1[g * 16 + 4 * t + 1]);
        bw[0][0][1] = pack_bf16(W1[g * 16 + 4 * t + 2],       W1[g * 16 + 4 * t + 3]);
        bw[0][1][0] = pack_bf16(W1[(g + 8) * 16 + 4 * t],     W1[(g + 8) * 16 + 4 * t + 1]);
        bw[0][1][1] = pack_bf16(W1[(g + 8) * 16 + 4 * t + 2], W1[(g + 8) * 16 + 4 * t + 3]);
        // layer 1: standard (C layout == A layout chaining)
        bw[1][0][0] = pack_bf16(W2[g * 16 + 2 * t],           W2[g * 16 + 2 * t + 1]);
        bw[1][0][1] = pack_bf16(W2[g * 16 + 2 * t + 8],       W2[g * 16 + 2 * t + 9]);
        bw[1][1][0] = pack_bf16(W2[(g + 8) * 16 + 2 * t],     W2[(g + 8) * 16 + 2 * t + 1]);
        bw[1][1][1] = pack_bf16(W2[(g + 8) * 16 + 2 * t + 8], W2[(g + 8) * 16 + 2 * t + 9]);
        // layer 2: n-permuted -> contiguous per-thread outputs (STG.128)
        const int pg = 4 * (g >> 1) + (g & 1);
        bw[2][0][0] = pack_bf16(W3[pg * 16 + 2 * t],           W3[pg * 16 + 2 * t + 1]);
        bw[2][0][1] = pack_bf16(W3[pg * 16 + 2 * t + 8],       W3[pg * 16 + 2 * t + 9]);
        bw[2][1][0] = pack_bf16(W3[(pg + 2) * 16 + 2 * t],     W3[(pg + 2) * 16 + 2 * t + 1]);
        bw[2][1][1] = pack_bf16(W3[(pg + 2) * 16 + 2 * t + 8], W3[(pg + 2) * 16 + 2 * t + 9]);

        bias[0][0] = b1[2 * t];     bias[0][1] = b1[2 * t + 1];
        bias[0][2] = b1[8 + 2 * t]; bias[0][3] = b1[8 + 2 * t + 1];
        bias[1][0] = b2[2 * t];     bias[1][1] = b2[2 * t + 1];
        bias[1][2] = b2[8 + 2 * t]; bias[1][3] = b2[8 + 2 * t + 1];
        bias[2][0] = b3[4 * t];     bias[2][1] = b3[4 * t + 1];
        bias[2][2] = b3[4 * t + 2]; bias[2][3] = b3[4 * t + 3];
    }

    const int tileBase0 = blockIdx.x * ABLK + wid * (TPW * 16);

    // ---- prefetch tile 0: A fragments + part indices -------------------------
    float4 pfA = make_float4(0.f, 0.f, 0.f, 0.f);
    float4 pfB = pfA;
    int    pfP0 = 0, pfP1 = 0;
    {
        const int r0 = tileBase0 + g, r1 = r0 + 8;
        if (r0 < nAtoms) {
            pfA  = *reinterpret_cast<const float4*>(atv + (size_t)r0 * 16 + 4 * t);
            pfP0 = part[r0];
        }
        if (r1 < nAtoms) {
            pfB  = *reinterpret_cast<const float4*>(atv + (size_t)r1 * 16 + 4 * t);
            pfP1 = part[r1];
        }
    }

#pragma unroll 1
    for (int tt = 0; tt < TPW; ++tt) {
        const int TB = tileBase0 + tt * 16;
        const int r0 = TB + g;
        const int r1 = TB + g + 8;
        const bool v0 = r0 < nAtoms;
        const bool v1 = r1 < nAtoms;

        // consume prefetch
        const float4 cA = pfA;
        const float4 cB = pfB;
        const int    p0 = pfP0;
        const int    p1 = pfP1;

        // issue next tile's loads early (overlap with this tile's compute)
        if (tt + 1 < TPW) {
            const int n0 = r0 + 16, n1 = r1 + 16;
            pfA = make_float4(0.f, 0.f, 0.f, 0.f);
            pfB = pfA;
            pfP0 = 0; pfP1 = 0;
            if (n0 < nAtoms) {
                pfA  = *reinterpret_cast<const float4*>(atv + (size_t)n0 * 16 + 4 * t);
                pfP0 = part[n0];
            }
            if (n1 < nAtoms) {
                pfB  = *reinterpret_cast<const float4*>(atv + (size_t)n1 * 16 + 4 * t);
                pfP1 = part[n1];
            }
        }

        // ---- A fragment (layer-0 permuted k) --------------------------------
        unsigned a0 = pack_bf16(cA.x, cA.y);
        unsigned a2 = pack_bf16(cA.z, cA.w);
        unsigned a1 = pack_bf16(cB.x, cB.y);
        unsigned a3 = pack_bf16(cB.z, cB.w);

        // ---- 3 chained layers; packed bf16x2 ELU between layers --------------
        float cl[4], ch[4];
#pragma unroll
        for (int l = 0; l < 3; ++l) {
            cl[0] = bias[l][0]; cl[1] = bias[l][1]; cl[2] = bias[l][0]; cl[3] = bias[l][1];
            ch[0] = bias[l][2]; ch[1] = bias[l][3]; ch[2] = bias[l][2]; ch[3] = bias[l][3];
            mma_16816(cl[0], cl[1], cl[2], cl[3], a0, a1, a2, a3, bw[l][0][0], bw[l][0][1]);
            mma_16816(ch[0], ch[1], ch[2], ch[3], a0, a1, a2, a3, bw[l][1][0], bw[l][1][1]);
            if (l < 2) {
                a0 = elu_bf16x2(pack_bf16(cl[0], cl[1]));
                a1 = elu_bf16x2(pack_bf16(cl[2], cl[3]));
                a2 = elu_bf16x2(pack_bf16(ch[0], ch[1]));
                a3 = elu_bf16x2(pack_bf16(ch[2], ch[3]));
            }
        }

        // ---- epilogue add from shared table ----------------------------------
        int pc0 = p0 < 0 ? 0 : (p0 >= tn ? tn - 1 : p0);
        int pc1 = p1 < 0 ? 0 : (p1 >= tn ? tn - 1 : p1);
        const float av0 = s_val[pc0];
        const float av1 = s_val[pc1];

        // ---- final ELU (fp32) + add + contiguous STG.128 stores --------------
        if (v0) {
            float4 s;
            s.x = elu1(cl[0]) + av0;
            s.y = elu1(cl[1]) + av0;
            s.z = elu1(ch[0]) + av0;
            s.w = elu1(ch[1]) + av0;
            *reinterpret_cast<float4*>(out + (size_t)r0 * 16 + 4 * t) = s;
        }
        if (v1) {
            float4 s;
            s.x = elu1(cl[2]) + av1;
            s.y = elu1(cl[3]) + av1;
            s.z = elu1(ch[2]) + av1;
            s.w = elu1(ch[3]) + av1;
            *reinterpret_cast<float4*>(out + (size_t)r1 * 16 + 4 * t) = s;
        }
    }
}

extern "C" void kernel_launch(void* const* d_in, const int* in_sizes, int n_in,
                              void* d_out, int out_size) {
    // ---- bind inputs by element count (order-independent) ------------------
    const float* Ws[3] = {nullptr, nullptr, nullptr};
    const float* bs[3] = {nullptr, nullptr, nullptr};
    const float* charge = nullptr;
    int wi = 0, bi = 0, chargeN = 1024;

    int bigIdx[2] = {-1, -1};
    long long bigSz[2] = {-1, -1};

    for (int i = 0; i < n_in; ++i) {
        long long s = in_sizes[i];
        if (s == 256 && wi < 3) {
            Ws[wi++] = (const float*)d_in[i];
        } else if (s == 16 && bi < 3) {
            bs[bi++] = (const float*)d_in[i];
        } else if (s >= 512 && s <= 65536 && s != 256) {
            charge = (const float*)d_in[i];
            chargeN = (int)s;
        } else if (s > 65536) {
            if (s > bigSz[0]) {
                bigSz[1] = bigSz[0]; bigIdx[1] = bigIdx[0];
                bigSz[0] = s;        bigIdx[0] = i;
            } else if (s > bigSz[1]) {
                bigSz[1] = s;        bigIdx[1] = i;
            }
        }
    }

    const float* atv  = (const float*)d_in[bigIdx[0]];  // 16*N elems
    const int*   part = (const int*)d_in[bigIdx[1]];    // N elems, int32
    float*       out  = (float*)d_out;

    int nAtoms = (int)bigSz[1];
    if ((long long)nAtoms * 16 != bigSz[0]) {
        nAtoms = (int)(bigSz[0] / 16);
    }

    int grid = (nAtoms + ABLK - 1) / ABLK;
    nodes_embedding_kernel<<<grid, BLOCK>>>(atv, charge, Ws[0], bs[0], Ws[1], bs[1],
                                            Ws[2], bs[2], part, out, nAtoms, chargeN);
}